// round 13
// baseline (speedup 1.0000x reference)
#include <cuda_runtime.h>
#include <cstdint>

// out = tanh(in @ Lr^T + br) + in @ Ld^T + bd + in
// Edge-flow scatter, grouped per target node:
//   per edge k (i=ei,j=ej): vr = wr_k*in[j]; vd = wd_k*in[i];
//     node j += (+vr, -vd)   [reaction, diffusion]
//     node i += (-vr, +vd)
// One vectorized CTA-SCOPE global reduction per endpoint (vector red is
// illegal in shared space). Target-split ownership makes every g_acc word
// private to one CTA, so cta-scope red + membar.cta is sufficient ordering —
// no gpu-scope fence drain (which ate the R12 win).

#define NN 207
#define NE 1722
#define NPAIRS (NE / 2)      // 861
#define BATCH 64
#define THREADS 512
#define HALF0 104            // half 0 owns nodes [0,104), half 1 owns [104,207)

__device__ float2 g_acc[BATCH][NN];   // (reaction, diffusion) accumulators

__device__ __forceinline__ float tanh_approx(float x) {
    float y;
    asm("tanh.approx.f32 %0, %1;" : "=f"(y) : "f"(x));
    return y;
}

__device__ __forceinline__ void red_cta_v2(float2* p, float a, float b) {
    asm volatile("red.relaxed.cta.global.add.v2.f32 [%0], {%1, %2};"
                 :: "l"(p), "f"(a), "f"(b) : "memory");
}

__global__ __launch_bounds__(THREADS)
void rd_k(const float* __restrict__ in,
          const float* __restrict__ wr,
          const float* __restrict__ wd,
          const float* __restrict__ br,
          const float* __restrict__ bd,
          const int*   __restrict__ ei,
          const int*   __restrict__ ej,
          float* __restrict__ out) {
    __shared__ float s_in[NN];

    const int tid   = threadIdx.x;
    const int batch = blockIdx.x >> 1;
    const int half  = blockIdx.x & 1;
    const int n_lo  = half ? HALF0 : 0;
    const int n_hi  = half ? NN : HALF0;

    // ---- prefetch edge pairs (high-MLP LDG.64 burst) ----
    const int kA = 2 * tid;                       // pairs [0,512)
    int2 iA = *reinterpret_cast<const int2*>(&ei[kA]);
    int2 jA = *reinterpret_cast<const int2*>(&ej[kA]);
    float2 rA = *reinterpret_cast<const float2*>(&wr[kA]);
    float2 dA = *reinterpret_cast<const float2*>(&wd[kA]);
    const bool hasB = (tid + THREADS) < NPAIRS;   // pairs [512,861)
    int2 iB; int2 jB; float2 rB; float2 dB;
    if (hasB) {
        const int kB = 2 * (tid + THREADS);
        iB = *reinterpret_cast<const int2*>(&ei[kB]);
        jB = *reinterpret_cast<const int2*>(&ej[kB]);
        rB = *reinterpret_cast<const float2*>(&wr[kB]);
        dB = *reinterpret_cast<const float2*>(&wd[kB]);
    }

    // ---- prefetch epilogue biases (latency hides under scatter) ----
    const int n_out = n_lo + tid;
    const bool owns = (n_out < n_hi);
    float brn = 0.0f, bdn = 0.0f;
    if (owns) {
        brn = br[n_out];
        bdn = bd[n_out];
    }

    // ---- load input row + zero my accumulator range ----
    if (tid < NN) s_in[tid] = in[batch * NN + tid];
    if (owns) {
        __stcg(&g_acc[batch][n_out], make_float2(0.0f, 0.0f));
    }
    __threadfence_block();    // zeroes ordered before this CTA's reds (cta scope)
    __syncthreads();

    // ---- scatter: one v2 cta-scope global red per in-half target node ----
    #define PROCESS(i_, j_, wr_, wd_)                               \
    do {                                                            \
        const int i = (i_), j = (j_);                               \
        const float vr = (wr_) * s_in[j];                           \
        const float vd = (wd_) * s_in[i];                           \
        if ((j >= HALF0) == half) red_cta_v2(&g_acc[batch][j],  vr, -vd); \
        if ((i >= HALF0) == half) red_cta_v2(&g_acc[batch][i], -vr,  vd); \
    } while (0)

    PROCESS(iA.x, jA.x, rA.x, dA.x);
    PROCESS(iA.y, jA.y, rA.y, dA.y);
    if (hasB) {
        PROCESS(iB.x, jB.x, rB.x, dB.x);
        PROCESS(iB.y, jB.y, rB.y, dB.y);
    }
    #undef PROCESS

    __threadfence_block();    // this thread's reds visible CTA-wide ...
    __syncthreads();          // ... and every thread's reds ordered before reads

    // ---- epilogue: read back (L2), finalize ----
    if (owns) {
        const float2 acc = __ldcg(&g_acc[batch][n_out]);
        out[batch * NN + n_out] =
            tanh_approx(acc.x + brn) + acc.y + bdn + s_in[n_out];
    }
}

extern "C" void kernel_launch(void* const* d_in, const int* in_sizes, int n_in,
                              void* d_out, int out_size) {
    const float* in_ = (const float*)d_in[0];
    const float* wr  = (const float*)d_in[1];
    const float* wd  = (const float*)d_in[2];
    const float* br  = (const float*)d_in[3];
    const float* bd  = (const float*)d_in[4];
    const int*   ei  = (const int*)d_in[5];
    const int*   ej  = (const int*)d_in[6];
    float* out = (float*)d_out;

    rd_k<<<BATCH * 2, THREADS>>>(in_, wr, wd, br, bd, ei, ej, out);
}